// round 3
// baseline (speedup 1.0000x reference)
#include <cuda_runtime.h>
#include <cuda_bf16.h>

// kspaceMap: out (32,129,128,128) f32.
//   channels 0..127: sep[b,w,h,w'] = (Re(t)cos(2pi w w'/128) - Im(t)sin(..))/128,
//                    t[b,h,w] = DFT_128(input[b,0,h,:])[w]
//   channel 128:     copy of input[b,1,h,:].   mask input unused.
//
// R3: (a) real-input symmetry: sep[128-w] == sep[w]; compute w=0..64, store twice.
//     (b) split-u DFT: all 128 threads do 64 MACs, smem combine; bin64 via shfl.
//     (c) packed f32x2 FMA (FFMA2) for value + rotation math in the store loop.

#define IM  128
#define BZ  32
#define CH_OUT 129

typedef unsigned long long u64;

static __device__ __forceinline__ u64 f2x(float a, float b) {
    u64 r; asm("mov.b64 %0, {%1, %2};" : "=l"(r) : "f"(a), "f"(b)); return r;
}
static __device__ __forceinline__ u64 mul2(u64 a, u64 b) {
    u64 d; asm("mul.rn.f32x2 %0, %1, %2;" : "=l"(d) : "l"(a), "l"(b)); return d;
}
static __device__ __forceinline__ u64 fma2(u64 a, u64 b, u64 c) {
    u64 d; asm("fma.rn.f32x2 %0, %1, %2, %3;" : "=l"(d) : "l"(a), "l"(b), "l"(c)); return d;
}
static __device__ __forceinline__ float2 unpk(u64 v) {
    float2 r; asm("mov.b64 {%0, %1}, %2;" : "=f"(r.x), "=f"(r.y) : "l"(v)); return r;
}

__global__ void __launch_bounds__(IM) kspace_kernel(const float* __restrict__ in,
                                                    float* __restrict__ out)
{
    const int bh  = blockIdx.x;
    const int b   = bh >> 7;
    const int h   = bh & (IM - 1);
    const int tid = threadIdx.x;

    __shared__ float  xs[IM];
    __shared__ float2 part[IM];      // DFT u-half partials
    __shared__ float2 tws[65];       // t_w / 128 for w = 0..64

    // Stage x row; fuse channel-128 passthrough copy.
    const unsigned r0 = (((unsigned)b * 2 + 0) * IM + h) * IM;
    const unsigned r1 = (((unsigned)b * 2 + 1) * IM + h) * IM;
    xs[tid] = in[r0 + tid];
    out[(((unsigned)b * CH_OUT + IM) * IM + h) * IM + tid] = in[r1 + tid];
    __syncthreads();

    // ---- DFT partials: thread = (bin w = tid&63, u-half = tid>>6), 64 MACs ----
    {
        const int w    = tid & 63;
        const int half = tid >> 6;
        float S, C;  sincospif((float)w * (1.0f / 64.0f), &S, &C);   // step theta_w
        float s, c;  sincospif((float)(w * half), &s, &c);           // start u0=64*half (exact)
        float re = 0.0f, im = 0.0f;
        const float* xu = xs + (half << 6);
        #pragma unroll 8
        for (int u = 0; u < 64; ++u) {
            const float xv = xu[u];                 // LDS broadcast
            re = fmaf(xv,  c, re);
            im = fmaf(xv, -s, im);
            const float cn = fmaf(c, C, -(s * S));
            s = fmaf(s, C, c * S);
            c = cn;
        }
        part[tid] = make_float2(re, im);
    }
    // Bin 64 by warp 3: t64 = sum x[u]*(-1)^u  (real)
    if (tid >= 96) {
        const int l = tid & 31;
        float v = xs[l] + xs[l + 32] + xs[l + 64] + xs[l + 96];
        if (l & 1) v = -v;
        #pragma unroll
        for (int o = 16; o > 0; o >>= 1)
            v += __shfl_xor_sync(0xffffffffu, v, o);
        if (l == 0) tws[64] = make_float2(v * (1.0f / IM), 0.0f);
    }
    __syncthreads();
    if (tid < 64) {
        const float2 a = part[tid], bb = part[tid + 64];
        tws[tid] = make_float2((a.x + bb.x) * (1.0f / IM), (a.y + bb.y) * (1.0f / IM));
    }
    __syncthreads();

    // ---- Store stage: warp j handles w = j, j+4, ... <= 64; lane owns w' = 4l..4l+3.
    //      Each value stored to channel w and (mirror) channel 128-w.
    {
        const int warp = tid >> 5;
        const int lane = tid & 31;

        float c0[4], s0[4], sc[4], ss[4];
        #pragma unroll
        for (int k = 0; k < 4; ++k) {
            const int wp = 4 * lane + k;
            sincospif((float)wp * (1.0f / 16.0f), &ss[k], &sc[k]);               // step (dw=4)
            sincospif((float)(warp * wp) * (1.0f / 64.0f), &s0[k], &c0[k]);      // start w=warp
        }
        u64 C01 = f2x(c0[0], c0[1]), S01 = f2x(s0[0], s0[1]);
        u64 C23 = f2x(c0[2], c0[3]), S23 = f2x(s0[2], s0[3]);
        const u64 SC01 = f2x(sc[0], sc[1]),  SS01 = f2x(ss[0], ss[1]);
        const u64 SC23 = f2x(sc[2], sc[3]),  SS23 = f2x(ss[2], ss[3]);
        const u64 NSS01 = f2x(-ss[0], -ss[1]), NSS23 = f2x(-ss[2], -ss[3]);

        float* p  = out + (((((unsigned)b * CH_OUT) + warp) * IM + h) * IM + 4u * lane);
        float* pm = out + (((((unsigned)b * CH_OUT) + (IM - warp)) * IM + h) * IM + 4u * lane);
        const unsigned step = 4u * IM * IM;          // 4 channels in floats

        for (int w = warp; w <= 64; w += 4) {
            const float2 tt = tws[w];                 // LDS broadcast
            const u64 trx = f2x(tt.x,  tt.x);
            const float nti = -tt.y;
            const u64 ntx = f2x(nti, nti);
            const u64 v01 = fma2(ntx, S01, mul2(trx, C01));
            const u64 v23 = fma2(ntx, S23, mul2(trx, C23));
            const float2 a = unpk(v01), bb = unpk(v23);
            const float4 vv = make_float4(a.x, a.y, bb.x, bb.y);
            *(float4*)p = vv;
            if (w >= 1 && w <= 63) *(float4*)pm = vv;  // warp-uniform predicate
            p  += step;
            pm -= step;
            const u64 nC01 = fma2(S01, NSS01, mul2(C01, SC01));
            S01 = fma2(C01, SS01, mul2(S01, SC01));
            C01 = nC01;
            const u64 nC23 = fma2(S23, NSS23, mul2(C23, SC23));
            S23 = fma2(C23, SS23, mul2(S23, SC23));
            C23 = nC23;
        }
    }
}

extern "C" void kernel_launch(void* const* d_in, const int* in_sizes, int n_in,
                              void* d_out, int out_size)
{
    const float* in  = (const float*)d_in[0];   // (32,2,128,128) f32
    float*       out = (float*)d_out;           // (32,129,128,128) f32
    (void)in_sizes; (void)n_in; (void)out_size;

    kspace_kernel<<<BZ * IM, IM>>>(in, out);
}